// round 8
// baseline (speedup 1.0000x reference)
#include <cuda_runtime.h>
#include <cuda_bf16.h>
#include <mma.h>
#include <math.h>
#include <cstdint>

using namespace nvcuda;

#define BATCH 2048
#define SEQ   80
#define UNITS 512
#define EMB   100
#define EMBP  128
#define BT    (BATCH*SEQ)
#define THREADS 512
#define SEQU  ((size_t)SEQ * UNITS)

// ---- scan tiling ----
#define BM 128
#define BN 64
#define NBLK 128                 // 16 clusters x 8 CTAs
#define LDSU 72
#define LDSA 72
#define ABUF 18432               // 128*72*2
#define SM_U    0                // 73728
#define SM_W    73728            // 73728
#define SM_A    147456           // 3*18432 = 55296
#define SCAN_SMEM 202752

// ---- layer-0 bulk tiling ----
#define GBN 128
#define LDBB 136
#define LDBA 72
#define LDBC 132
#define BULK_ABUF 18432
#define GM_B 0
#define GM_A 139264
#define BULK_SMEM 194560

// ---------------- persistent device scratch ----------------
__device__ __nv_bfloat16 g_X[(size_t)BT * EMBP];
__device__ __nv_bfloat16 g_Z[(size_t)BT * UNITS];
__device__ __nv_bfloat16 g_H[(size_t)BT * UNITS];
__device__ __nv_bfloat16 g_W1p[EMBP * UNITS];
__device__ __nv_bfloat16 g_W[3][UNITS * UNITS];   // g_W[l] = Wm[l+1]
__device__ __nv_bfloat16 g_U[4][UNITS * UNITS];

// ---------------- helpers ----------------
__device__ __forceinline__ uint32_t smem_u32(const void* p) {
    uint32_t a;
    asm("{ .reg .u64 t; cvta.to.shared.u64 t, %1; cvt.u32.u64 %0, t; }" : "=r"(a) : "l"(p));
    return a;
}
__device__ __forceinline__ void cp16(uint32_t dst, const void* src) {
    asm volatile("cp.async.cg.shared.global [%0], [%1], 16;" :: "r"(dst), "l"(src));
}
#define CP_COMMIT() asm volatile("cp.async.commit_group;" ::: "memory")
#define CP_WAIT1()  asm volatile("cp.async.wait_group 1;" ::: "memory")
#define CP_WAIT0()  asm volatile("cp.async.wait_group 0;" ::: "memory")
#define CL_ARRIVE() asm volatile("barrier.cluster.arrive.aligned;" ::: "memory")
#define CL_WAIT()   asm volatile("barrier.cluster.wait.aligned;" ::: "memory")

__device__ __forceinline__ float tanhfast(float x) {
    float y;
    asm("tanh.approx.f32 %0, %1;" : "=f"(y) : "f"(x));
    return y;
}

// ---------------- embed + weight prep ----------------
__global__ void embed_kernel(const int* __restrict__ tokens, const float* __restrict__ emb) {
    size_t idx = (size_t)blockIdx.x * blockDim.x + threadIdx.x;
    if (idx >= (size_t)BT * EMBP) return;
    size_t row = idx >> 7;
    int col = (int)(idx & 127);
    int tok = tokens[row];
    float v = (col < EMB) ? emb[(size_t)tok * EMB + col] : 0.f;
    g_X[idx] = __float2bfloat16(v);
}

__global__ void prep_all(const float* __restrict__ W1, const float* __restrict__ W2,
                         const float* __restrict__ W3, const float* __restrict__ W4,
                         const float* __restrict__ U1, const float* __restrict__ U2,
                         const float* __restrict__ U3, const float* __restrict__ U4) {
    int y = blockIdx.y;
    int idx = blockIdx.x * blockDim.x + threadIdx.x;
    if (y == 0) {
        if (idx < EMBP * UNITS) {
            int k = idx >> 9, n = idx & 511;
            g_W1p[idx] = __float2bfloat16(k < EMB ? W1[k * UNITS + n] : 0.f);
        }
    } else if (y <= 3) {
        const float* s = (y == 1) ? W2 : (y == 2) ? W3 : W4;
        if (idx < UNITS * UNITS) g_W[y - 1][idx] = __float2bfloat16(s[idx]);
    } else {
        const float* s = (y == 4) ? U1 : (y == 5) ? U2 : (y == 6) ? U3 : U4;
        if (idx < UNITS * UNITS) g_U[y - 4][idx] = __float2bfloat16(s[idx]);
    }
}

// ---------------- layer-0 bulk GEMM: g_Z = X @ W1p (K=128) ----------------
__global__ __launch_bounds__(THREADS, 1) void gemm0() {
    extern __shared__ __align__(16) unsigned char smraw[];
    __nv_bfloat16* sB = (__nv_bfloat16*)(smraw + GM_B);
    float*         sC = (float*)(smraw + GM_B);

    const __nv_bfloat16* Ag = g_X;
    const __nv_bfloat16* Bg = g_W1p;
    const int K = EMBP, aStride = EMBP, KC = 2;

    const int n0 = blockIdx.x * GBN;
    const int m0 = blockIdx.y * BM;
    const int tid = threadIdx.x;
    const int wid = tid >> 5;
    const int wm = wid & 3, wn = wid >> 2;

    const uint32_t sbase = smem_u32(smraw);
    const uint32_t aBase = sbase + GM_A;

    for (int i = tid; i < K * 16; i += THREADS) {
        int r = i >> 4, c = i & 15;
        cp16(sbase + GM_B + r * (LDBB * 2) + c * 16, Bg + (size_t)r * UNITS + n0 + c * 8);
    }
    {
        #pragma unroll
        for (int j = 0; j < 2; j++) {
            int i = tid + j * THREADS;
            int r = i >> 3, c = i & 7;
            cp16(aBase + r * (LDBA * 2) + c * 16, Ag + (size_t)(m0 + r) * aStride + c * 8);
        }
    }
    CP_COMMIT();

    wmma::fragment<wmma::accumulator, 16, 16, 16, float> acc[2][2];
    #pragma unroll
    for (int i = 0; i < 2; i++)
        #pragma unroll
        for (int j = 0; j < 2; j++) wmma::fill_fragment(acc[i][j], 0.f);

    int buf = 0;
    for (int kc = 0; kc < KC; kc++) {
        if (kc + 1 < KC) {
            int nb = buf + 1;
            #pragma unroll
            for (int j = 0; j < 2; j++) {
                int i = tid + j * THREADS;
                int r = i >> 3, c = i & 7;
                cp16(aBase + nb * BULK_ABUF + r * (LDBA * 2) + c * 16,
                     Ag + (size_t)(m0 + r) * aStride + (kc + 1) * 64 + c * 8);
            }
            CP_COMMIT();
            CP_WAIT1();
        } else {
            CP_WAIT0();
        }
        __syncthreads();

        const __nv_bfloat16* sA = (const __nv_bfloat16*)(smraw + GM_A + buf * BULK_ABUF);
        #pragma unroll
        for (int kk = 0; kk < 64; kk += 16) {
            wmma::fragment<wmma::matrix_a, 16, 16, 16, __nv_bfloat16, wmma::row_major> a0, a1;
            wmma::fragment<wmma::matrix_b, 16, 16, 16, __nv_bfloat16, wmma::row_major> b0, b1;
            wmma::load_matrix_sync(a0, sA + (wm * 32) * LDBA + kk, LDBA);
            wmma::load_matrix_sync(a1, sA + (wm * 32 + 16) * LDBA + kk, LDBA);
            wmma::load_matrix_sync(b0, sB + (kc * 64 + kk) * LDBB + wn * 32, LDBB);
            wmma::load_matrix_sync(b1, sB + (kc * 64 + kk) * LDBB + wn * 32 + 16, LDBB);
            wmma::mma_sync(acc[0][0], a0, b0, acc[0][0]);
            wmma::mma_sync(acc[0][1], a0, b1, acc[0][1]);
            wmma::mma_sync(acc[1][0], a1, b0, acc[1][0]);
            wmma::mma_sync(acc[1][1], a1, b1, acc[1][1]);
        }
        buf++;
    }
    __syncthreads();

    #pragma unroll
    for (int i = 0; i < 2; i++)
        #pragma unroll
        for (int j = 0; j < 2; j++)
            wmma::store_matrix_sync(&sC[(wm * 32 + i * 16) * LDBC + wn * 32 + j * 16],
                                    acc[i][j], LDBC, wmma::mem_row_major);
    __syncthreads();

    {
        const int erow = tid >> 2;
        const int ecb  = (tid & 3) * 32;
        const float* s = &sC[erow * LDBC + ecb];
        __nv_bfloat162 p[16];
        #pragma unroll
        for (int q = 0; q < 16; q++) p[q] = __floats2bfloat162_rn(s[2*q], s[2*q+1]);
        __nv_bfloat16* dst = g_Z + (size_t)(m0 + erow) * UNITS + n0 + ecb;
        #pragma unroll
        for (int q = 0; q < 4; q++)
            *(uint4*)(dst + q * 8) = *(uint4*)&p[q * 4];
    }
}

// ---------------- fused persistent scan: cluster barrier + register epilogue ----------------
__global__ __launch_bounds__(THREADS, 1) __cluster_dims__(8, 1, 1)
void scan_layer(int layer, const float* __restrict__ bias, int hasZ) {
    extern __shared__ __align__(16) unsigned char smraw[];
    __nv_bfloat16* sU = (__nv_bfloat16*)(smraw + SM_U);
    __nv_bfloat16* sW = (__nv_bfloat16*)(smraw + SM_W);
    const uint32_t aBase = smem_u32(smraw) + SM_A;

    const int tid = threadIdx.x;
    const int wid = tid >> 5, lane = tid & 31;
    const int bid = blockIdx.x;
    const int n0 = (bid & 7) * BN;
    const int m0 = (bid >> 3) * BM;
    const int wm = wid & 3, wn = wid >> 2;
    const int r0 = lane >> 2, c0 = (lane & 3) * 2;

    // stage U and (if hasZ) Wnext
    {
        const __nv_bfloat16* U = g_U[layer];
        #pragma unroll
        for (int j = 0; j < 8; j++) {
            int i = tid + j * THREADS;
            int r = i >> 3, c = i & 7;
            *(uint4*)&sU[r * LDSU + c * 8] = *(const uint4*)(U + (size_t)r * UNITS + n0 + c * 8);
        }
        if (hasZ) {
            const __nv_bfloat16* W = g_W[layer];
            #pragma unroll
            for (int j = 0; j < 8; j++) {
                int i = tid + j * THREADS;
                int r = i >> 3, c = i & 7;
                *(uint4*)&sW[r * LDSU + c * 8] = *(const uint4*)(W + (size_t)r * UNITS + n0 + c * 8);
            }
        }
    }

    // bias in registers (cols colg+{0,1,8,9})
    const int colg = n0 + wn * 16 + c0;
    const float bA0 = bias[colg],     bA1 = bias[colg + 1];
    const float bB0 = bias[colg + 8], bB1 = bias[colg + 9];

    // per-thread element bases: rows m0 + wm*32 + r0 + {0,8,16,24}
    size_t base[4];
    #pragma unroll
    for (int k = 0; k < 4; k++)
        base[k] = (size_t)(m0 + wm * 32 + r0 + k * 8) * SEQU + colg;

    __syncthreads();

    const size_t aStride = SEQU;
    const int itMax = hasZ ? SEQ : (SEQ - 1);

    for (int it = 0; it <= itMax; it++) {
        const bool doRec = (it < SEQ);
        const bool doZ   = (hasZ && it >= 1);

        if (it == 0) {
            // h_0 = tanh(Z_0 + b)
            #pragma unroll
            for (int f = 0; f < 2; f++)
                #pragma unroll
                for (int e = 0; e < 4; e++) {
                    size_t addr = base[f * 2 + (e & 1)] + ((e & 2) ? 8 : 0);
                    uint32_t zv = *(const uint32_t*)(g_Z + addr);
                    __nv_bfloat162 zb = *(__nv_bfloat162*)&zv;
                    float blo = (e & 2) ? bB0 : bA0, bhi = (e & 2) ? bB1 : bA1;
                    __nv_bfloat162 o = __floats2bfloat162_rn(
                        tanhfast(__low2float(zb) + blo), tanhfast(__high2float(zb) + bhi));
                    *(__nv_bfloat162*)(g_H + addr) = o;
                }
            CL_ARRIVE();
            CL_WAIT();
            continue;
        }

        const __nv_bfloat16* A = g_H + (size_t)(it - 1) * UNITS;

        // prologue: A chunks 0,1
        #pragma unroll
        for (int cidx = 0; cidx < 2; cidx++) {
            #pragma unroll
            for (int j = 0; j < 2; j++) {
                int i = tid + j * THREADS;
                int r = i >> 3, c = i & 7;
                cp16(aBase + cidx * ABUF + r * (LDSA * 2) + c * 16,
                     A + (size_t)(m0 + r) * aStride + cidx * 64 + c * 8);
            }
            CP_COMMIT();
        }

        // own-Z prefetch (register epilogue operands)
        uint32_t zr[8];
        if (doRec) {
            #pragma unroll
            for (int f = 0; f < 2; f++)
                #pragma unroll
                for (int e = 0; e < 4; e++)
                    zr[f * 4 + e] = *(const uint32_t*)(
                        g_Z + base[f * 2 + (e & 1)] + (size_t)it * UNITS + ((e & 2) ? 8 : 0));
        }

        wmma::fragment<wmma::accumulator, 16, 16, 16, float> accR[2], accZ[2];
        if (doRec) { wmma::fill_fragment(accR[0], 0.f); wmma::fill_fragment(accR[1], 0.f); }
        if (doZ)   { wmma::fill_fragment(accZ[0], 0.f); wmma::fill_fragment(accZ[1], 0.f); }

        for (int kc = 0; kc < 8; kc++) {
            if (kc < 7) CP_WAIT1(); else CP_WAIT0();
            __syncthreads();
            if (kc + 2 < 8) {
                int nb = (kc + 2) % 3;
                #pragma unroll
                for (int j = 0; j < 2; j++) {
                    int i = tid + j * THREADS;
                    int r = i >> 3, c = i & 7;
                    cp16(aBase + nb * ABUF + r * (LDSA * 2) + c * 16,
                         A + (size_t)(m0 + r) * aStride + (kc + 2) * 64 + c * 8);
                }
                CP_COMMIT();
            }
            const __nv_bfloat16* sA  = (const __nv_bfloat16*)(smraw + SM_A + (kc % 3) * ABUF);
            const __nv_bfloat16* sUw = sU + (kc * 64) * LDSU + wn * 16;
            const __nv_bfloat16* sWw = sW + (kc * 64) * LDSU + wn * 16;
            #pragma unroll
            for (int kk = 0; kk < 64; kk += 16) {
                wmma::fragment<wmma::matrix_a, 16, 16, 16, __nv_bfloat16, wmma::row_major> a0, a1;
                wmma::load_matrix_sync(a0, sA + (wm * 32) * LDSA + kk, LDSA);
                wmma::load_matrix_sync(a1, sA + (wm * 32 + 16) * LDSA + kk, LDSA);
                if (doRec) {
                    wmma::fragment<wmma::matrix_b, 16, 16, 16, __nv_bfloat16, wmma::row_major> bU;
                    wmma::load_matrix_sync(bU, sUw + kk * LDSU, LDSU);
                    wmma::mma_sync(accR[0], a0, bU, accR[0]);
                    wmma::mma_sync(accR[1], a1, bU, accR[1]);
                }
                if (doZ) {
                    wmma::fragment<wmma::matrix_b, 16, 16, 16, __nv_bfloat16, wmma::row_major> bW;
                    wmma::load_matrix_sync(bW, sWw + kk * LDSU, LDSU);
                    wmma::mma_sync(accZ[0], a0, bW, accZ[0]);
                    wmma::mma_sync(accZ[1], a1, bW, accZ[1]);
                }
            }
        }

        // register epilogue: h_t = tanh(R + Z + b), straight from fragments
        if (doRec) {
            #pragma unroll
            for (int f = 0; f < 2; f++)
                #pragma unroll
                for (int e = 0; e < 4; e++) {
                    size_t addr = base[f * 2 + (e & 1)] + (size_t)it * UNITS + ((e & 2) ? 8 : 0);
                    uint32_t zv = zr[f * 4 + e];
                    __nv_bfloat162 zb = *(__nv_bfloat162*)&zv;
                    float blo = (e & 2) ? bB0 : bA0, bhi = (e & 2) ? bB1 : bA1;
                    __nv_bfloat162 o = __floats2bfloat162_rn(
                        tanhfast(accR[f].x[e * 2]     + __low2float(zb)  + blo),
                        tanhfast(accR[f].x[e * 2 + 1] + __high2float(zb) + bhi));
                    *(__nv_bfloat162*)(g_H + addr) = o;
                }
        }

        const bool needBar = doRec && (hasZ || it < SEQ - 1);
        if (needBar) CL_ARRIVE();          // release: h stores visible to cluster

        if (doZ) {
            // Z^{l+1}_{it-1} -> g_Z (fills the barrier-wait gap)
            #pragma unroll
            for (int f = 0; f < 2; f++)
                #pragma unroll
                for (int e = 0; e < 4; e++) {
                    size_t addr = base[f * 2 + (e & 1)] + (size_t)(it - 1) * UNITS + ((e & 2) ? 8 : 0);
                    __nv_bfloat162 o = __floats2bfloat162_rn(accZ[f].x[e * 2], accZ[f].x[e * 2 + 1]);
                    *(__nv_bfloat162*)(g_Z + addr) = o;
                }
        }

        if (needBar) CL_WAIT();            // acquire + implicit block-wide sync
        else __syncthreads();              // protect A-buffer reuse on final iterations
    }
}

// ---------------- head ----------------
__global__ void head(const float* __restrict__ Wo, const float* __restrict__ bo,
                     float* __restrict__ out) {
    int gt = blockIdx.x * blockDim.x + threadIdx.x;
    int w = gt >> 5, lane = gt & 31;
    if (w >= BATCH) return;
    const __nv_bfloat16* h = g_H + ((size_t)w * SEQ + (SEQ - 1)) * UNITS;
    float s = 0.f;
    for (int k = lane; k < UNITS; k += 32)
        s += __bfloat162float(h[k]) * Wo[k];
    #pragma unroll
    for (int o = 16; o; o >>= 1) s += __shfl_xor_sync(0xffffffffu, s, o);
    if (lane == 0) out[w] = 1.f / (1.f + expf(-(s + bo[0])));
}

// ---------------- launch ----------------
extern "C" void kernel_launch(void* const* d_in, const int* in_sizes, int n_in,
                              void* d_out, int out_size) {
    const int*   tokens = (const int*)d_in[0];
    const float* emb    = (const float*)d_in[1];
    const float* Wm[4]  = {(const float*)d_in[2],  (const float*)d_in[5],
                           (const float*)d_in[8],  (const float*)d_in[11]};
    const float* Um[4]  = {(const float*)d_in[3],  (const float*)d_in[6],
                           (const float*)d_in[9],  (const float*)d_in[12]};
    const float* bm[4]  = {(const float*)d_in[4],  (const float*)d_in[7],
                           (const float*)d_in[10], (const float*)d_in[13]};
    const float* Wo = (const float*)d_in[14];
    const float* bo = (const float*)d_in[15];
    float* out = (float*)d_out;

    cudaFuncSetAttribute(gemm0,      cudaFuncAttributeMaxDynamicSharedMemorySize, BULK_SMEM);
    cudaFuncSetAttribute(scan_layer, cudaFuncAttributeMaxDynamicSharedMemorySize, SCAN_SMEM);

    embed_kernel<<<(int)(((size_t)BT * EMBP + 255) / 256), 256>>>(tokens, emb);

    dim3 pg(1024, 8);
    prep_all<<<pg, 256>>>(Wm[0], Wm[1], Wm[2], Wm[3], Um[0], Um[1], Um[2], Um[3]);

    dim3 gin(UNITS / GBN, BT / BM);     // (4, 1280)
    gemm0<<<gin, THREADS, BULK_SMEM>>>();

    for (int l = 0; l < 4; l++) {
        int hasZ = (l < 3) ? 1 : 0;
        scan_layer<<<NBLK, THREADS, SCAN_SMEM>>>(l, bm[l], hasZ);
    }
    head<<<(BATCH * 32 + 255) / 256, 256>>>(Wo, bo, out);
}

// round 9
// speedup vs baseline: 1.2348x; 1.2348x over previous
#include <cuda_runtime.h>
#include <cuda_bf16.h>
#include <mma.h>
#include <math.h>
#include <cstdint>

using namespace nvcuda;

#define BATCH 2048
#define SEQ   80
#define UNITS 512
#define EMB   100
#define EMBP  128
#define BT    (BATCH*SEQ)
#define THREADS 512
#define SEQU  ((size_t)SEQ * UNITS)

// ---- scan tiling ----
#define BM 128
#define BN 64
#define NBLK 128                 // 16 m-groups x 8 n-tiles
#define LDSU 72
#define LDSA 72
#define ABUF 18432               // 128*72*2
#define SM_U    0                // 73728
#define SM_W    73728            // 73728
#define SM_A    147456           // 3*18432 = 55296
#define SCAN_SMEM 202752

// ---- layer-0 bulk tiling ----
#define GBN 128
#define LDBB 136
#define LDBA 72
#define LDBC 132
#define BULK_ABUF 18432
#define GM_B 0
#define GM_A 139264
#define BULK_SMEM 194560

// ---------------- persistent device scratch ----------------
__device__ __nv_bfloat16 g_X[(size_t)BT * EMBP];
__device__ __nv_bfloat16 g_Z[(size_t)BT * UNITS];
__device__ __nv_bfloat16 g_H[(size_t)BT * UNITS];
__device__ __nv_bfloat16 g_W1p[EMBP * UNITS];
__device__ __nv_bfloat16 g_W[3][UNITS * UNITS];   // g_W[l] = Wm[l+1]
__device__ __nv_bfloat16 g_U[4][UNITS * UNITS];
__device__ unsigned int  g_arr[16];

// ---------------- helpers ----------------
__device__ __forceinline__ uint32_t smem_u32(const void* p) {
    uint32_t a;
    asm("{ .reg .u64 t; cvta.to.shared.u64 t, %1; cvt.u32.u64 %0, t; }" : "=r"(a) : "l"(p));
    return a;
}
__device__ __forceinline__ void cp16(uint32_t dst, const void* src) {
    asm volatile("cp.async.cg.shared.global [%0], [%1], 16;" :: "r"(dst), "l"(src));
}
#define CP_COMMIT() asm volatile("cp.async.commit_group;" ::: "memory")
#define CP_WAIT1()  asm volatile("cp.async.wait_group 1;" ::: "memory")
#define CP_WAIT0()  asm volatile("cp.async.wait_group 0;" ::: "memory")

__device__ __forceinline__ float tanhfast(float x) {
    float y;
    asm("tanh.approx.f32 %0, %1;" : "=f"(y) : "f"(x));
    return y;
}

// ---------------- embed + weight prep ----------------
__global__ void embed_kernel(const int* __restrict__ tokens, const float* __restrict__ emb) {
    size_t idx = (size_t)blockIdx.x * blockDim.x + threadIdx.x;
    if (idx >= (size_t)BT * EMBP) return;
    size_t row = idx >> 7;
    int col = (int)(idx & 127);
    int tok = tokens[row];
    float v = (col < EMB) ? emb[(size_t)tok * EMB + col] : 0.f;
    g_X[idx] = __float2bfloat16(v);
}

__global__ void prep_all(const float* __restrict__ W1, const float* __restrict__ W2,
                         const float* __restrict__ W3, const float* __restrict__ W4,
                         const float* __restrict__ U1, const float* __restrict__ U2,
                         const float* __restrict__ U3, const float* __restrict__ U4) {
    int y = blockIdx.y;
    int idx = blockIdx.x * blockDim.x + threadIdx.x;
    if (y == 0) {
        if (idx < EMBP * UNITS) {
            int k = idx >> 9, n = idx & 511;
            g_W1p[idx] = __float2bfloat16(k < EMB ? W1[k * UNITS + n] : 0.f);
        }
    } else if (y <= 3) {
        const float* s = (y == 1) ? W2 : (y == 2) ? W3 : W4;
        if (idx < UNITS * UNITS) g_W[y - 1][idx] = __float2bfloat16(s[idx]);
    } else {
        const float* s = (y == 4) ? U1 : (y == 5) ? U2 : (y == 6) ? U3 : U4;
        if (idx < UNITS * UNITS) g_U[y - 4][idx] = __float2bfloat16(s[idx]);
    }
}

// ---------------- layer-0 bulk GEMM: g_Z = X @ W1p (K=128) ----------------
__global__ __launch_bounds__(THREADS, 1) void gemm0() {
    extern __shared__ __align__(16) unsigned char smraw[];
    __nv_bfloat16* sB = (__nv_bfloat16*)(smraw + GM_B);
    float*         sC = (float*)(smraw + GM_B);

    const __nv_bfloat16* Ag = g_X;
    const __nv_bfloat16* Bg = g_W1p;
    const int K = EMBP, aStride = EMBP, KC = 2;

    const int n0 = blockIdx.x * GBN;
    const int m0 = blockIdx.y * BM;
    const int tid = threadIdx.x;
    const int wid = tid >> 5;
    const int wm = wid & 3, wn = wid >> 2;

    const uint32_t sbase = smem_u32(smraw);
    const uint32_t aBase = sbase + GM_A;

    for (int i = tid; i < K * 16; i += THREADS) {
        int r = i >> 4, c = i & 15;
        cp16(sbase + GM_B + r * (LDBB * 2) + c * 16, Bg + (size_t)r * UNITS + n0 + c * 8);
    }
    {
        #pragma unroll
        for (int j = 0; j < 2; j++) {
            int i = tid + j * THREADS;
            int r = i >> 3, c = i & 7;
            cp16(aBase + r * (LDBA * 2) + c * 16, Ag + (size_t)(m0 + r) * aStride + c * 8);
        }
    }
    CP_COMMIT();

    wmma::fragment<wmma::accumulator, 16, 16, 16, float> acc[2][2];
    #pragma unroll
    for (int i = 0; i < 2; i++)
        #pragma unroll
        for (int j = 0; j < 2; j++) wmma::fill_fragment(acc[i][j], 0.f);

    int buf = 0;
    for (int kc = 0; kc < KC; kc++) {
        if (kc + 1 < KC) {
            int nb = buf + 1;
            #pragma unroll
            for (int j = 0; j < 2; j++) {
                int i = tid + j * THREADS;
                int r = i >> 3, c = i & 7;
                cp16(aBase + nb * BULK_ABUF + r * (LDBA * 2) + c * 16,
                     Ag + (size_t)(m0 + r) * aStride + (kc + 1) * 64 + c * 8);
            }
            CP_COMMIT();
            CP_WAIT1();
        } else {
            CP_WAIT0();
        }
        __syncthreads();

        const __nv_bfloat16* sA = (const __nv_bfloat16*)(smraw + GM_A + buf * BULK_ABUF);
        #pragma unroll
        for (int kk = 0; kk < 64; kk += 16) {
            wmma::fragment<wmma::matrix_a, 16, 16, 16, __nv_bfloat16, wmma::row_major> a0, a1;
            wmma::fragment<wmma::matrix_b, 16, 16, 16, __nv_bfloat16, wmma::row_major> b0, b1;
            wmma::load_matrix_sync(a0, sA + (wm * 32) * LDBA + kk, LDBA);
            wmma::load_matrix_sync(a1, sA + (wm * 32 + 16) * LDBA + kk, LDBA);
            wmma::load_matrix_sync(b0, sB + (kc * 64 + kk) * LDBB + wn * 32, LDBB);
            wmma::load_matrix_sync(b1, sB + (kc * 64 + kk) * LDBB + wn * 32 + 16, LDBB);
            wmma::mma_sync(acc[0][0], a0, b0, acc[0][0]);
            wmma::mma_sync(acc[0][1], a0, b1, acc[0][1]);
            wmma::mma_sync(acc[1][0], a1, b0, acc[1][0]);
            wmma::mma_sync(acc[1][1], a1, b1, acc[1][1]);
        }
        buf++;
    }
    __syncthreads();

    #pragma unroll
    for (int i = 0; i < 2; i++)
        #pragma unroll
        for (int j = 0; j < 2; j++)
            wmma::store_matrix_sync(&sC[(wm * 32 + i * 16) * LDBC + wn * 32 + j * 16],
                                    acc[i][j], LDBC, wmma::mem_row_major);
    __syncthreads();

    {
        const int erow = tid >> 2;
        const int ecb  = (tid & 3) * 32;
        const float* s = &sC[erow * LDBC + ecb];
        __nv_bfloat162 p[16];
        #pragma unroll
        for (int q = 0; q < 16; q++) p[q] = __floats2bfloat162_rn(s[2*q], s[2*q+1]);
        __nv_bfloat16* dst = g_Z + (size_t)(m0 + erow) * UNITS + n0 + ecb;
        #pragma unroll
        for (int q = 0; q < 4; q++)
            *(uint4*)(dst + q * 8) = *(uint4*)&p[q * 4];
    }
}

// ---------------- fused persistent scan: atomic group barrier + register epilogue ----------------
__global__ __launch_bounds__(THREADS, 1)
void scan_layer(int layer, const float* __restrict__ bias, int hasZ, unsigned barBase) {
    extern __shared__ __align__(16) unsigned char smraw[];
    __nv_bfloat16* sU = (__nv_bfloat16*)(smraw + SM_U);
    __nv_bfloat16* sW = (__nv_bfloat16*)(smraw + SM_W);
    const uint32_t aBase = smem_u32(smraw) + SM_A;

    const int tid = threadIdx.x;
    const int wid = tid >> 5, lane = tid & 31;
    const int bid = blockIdx.x;
    const int n0 = (bid & 7) * BN;
    const int mg = bid >> 3;
    const int m0 = mg * BM;
    const int wm = wid & 3, wn = wid >> 2;
    const int r0 = lane >> 2, c0 = (lane & 3) * 2;

    // stage U and (if hasZ) Wnext
    {
        const __nv_bfloat16* U = g_U[layer];
        #pragma unroll
        for (int j = 0; j < 8; j++) {
            int i = tid + j * THREADS;
            int r = i >> 3, c = i & 7;
            *(uint4*)&sU[r * LDSU + c * 8] = *(const uint4*)(U + (size_t)r * UNITS + n0 + c * 8);
        }
        if (hasZ) {
            const __nv_bfloat16* W = g_W[layer];
            #pragma unroll
            for (int j = 0; j < 8; j++) {
                int i = tid + j * THREADS;
                int r = i >> 3, c = i & 7;
                *(uint4*)&sW[r * LDSU + c * 8] = *(const uint4*)(W + (size_t)r * UNITS + n0 + c * 8);
            }
        }
    }

    // bias in registers (cols colg+{0,1,8,9})
    const int colg = n0 + wn * 16 + c0;
    const float bA0 = bias[colg],     bA1 = bias[colg + 1];
    const float bB0 = bias[colg + 8], bB1 = bias[colg + 9];

    // per-thread element bases: rows m0 + wm*32 + r0 + {0,8,16,24}
    size_t base[4];
    #pragma unroll
    for (int k = 0; k < 4; k++)
        base[k] = (size_t)(m0 + wm * 32 + r0 + k * 8) * SEQU + colg;

    __syncthreads();

    const size_t aStride = SEQU;
    const int itMax = hasZ ? SEQ : (SEQ - 1);
    unsigned tgt = barBase;

    for (int it = 0; it <= itMax; it++) {
        const bool doRec = (it < SEQ);
        const bool doZ   = (hasZ && it >= 1);

        if (it == 0) {
            // h_0 = tanh(Z_0 + b)
            #pragma unroll
            for (int f = 0; f < 2; f++)
                #pragma unroll
                for (int e = 0; e < 4; e++) {
                    size_t addr = base[f * 2 + (e & 1)] + ((e & 2) ? 8 : 0);
                    uint32_t zv = *(const uint32_t*)(g_Z + addr);
                    __nv_bfloat162 zb = *(__nv_bfloat162*)&zv;
                    float blo = (e & 2) ? bB0 : bA0, bhi = (e & 2) ? bB1 : bA1;
                    __nv_bfloat162 o = __floats2bfloat162_rn(
                        tanhfast(__low2float(zb) + blo), tanhfast(__high2float(zb) + bhi));
                    *(__nv_bfloat162*)(g_H + addr) = o;
                }
            tgt += 8;
            __syncthreads();
            if (tid == 0) {
                __threadfence();
                atomicAdd(&g_arr[mg], 1u);
                volatile unsigned int* p = &g_arr[mg];
                while (*p < tgt) { }
                __threadfence();
            }
            __syncthreads();
            continue;
        }

        const __nv_bfloat16* A = g_H + (size_t)(it - 1) * UNITS;

        // prologue: A chunks 0,1
        #pragma unroll
        for (int cidx = 0; cidx < 2; cidx++) {
            #pragma unroll
            for (int j = 0; j < 2; j++) {
                int i = tid + j * THREADS;
                int r = i >> 3, c = i & 7;
                cp16(aBase + cidx * ABUF + r * (LDSA * 2) + c * 16,
                     A + (size_t)(m0 + r) * aStride + cidx * 64 + c * 8);
            }
            CP_COMMIT();
        }

        // own-Z prefetch (register epilogue operands)
        uint32_t zr[8];
        if (doRec) {
            #pragma unroll
            for (int f = 0; f < 2; f++)
                #pragma unroll
                for (int e = 0; e < 4; e++)
                    zr[f * 4 + e] = *(const uint32_t*)(
                        g_Z + base[f * 2 + (e & 1)] + (size_t)it * UNITS + ((e & 2) ? 8 : 0));
        }

        wmma::fragment<wmma::accumulator, 16, 16, 16, float> accR[2], accZ[2];
        if (doRec) { wmma::fill_fragment(accR[0], 0.f); wmma::fill_fragment(accR[1], 0.f); }
        if (doZ)   { wmma::fill_fragment(accZ[0], 0.f); wmma::fill_fragment(accZ[1], 0.f); }

        for (int kc = 0; kc < 8; kc++) {
            if (kc < 7) CP_WAIT1(); else CP_WAIT0();
            __syncthreads();
            if (kc + 2 < 8) {
                int nb = (kc + 2) % 3;
                #pragma unroll
                for (int j = 0; j < 2; j++) {
                    int i = tid + j * THREADS;
                    int r = i >> 3, c = i & 7;
                    cp16(aBase + nb * ABUF + r * (LDSA * 2) + c * 16,
                         A + (size_t)(m0 + r) * aStride + (kc + 2) * 64 + c * 8);
                }
                CP_COMMIT();
            }
            const __nv_bfloat16* sA  = (const __nv_bfloat16*)(smraw + SM_A + (kc % 3) * ABUF);
            const __nv_bfloat16* sUw = sU + (kc * 64) * LDSU + wn * 16;
            const __nv_bfloat16* sWw = sW + (kc * 64) * LDSU + wn * 16;
            #pragma unroll
            for (int kk = 0; kk < 64; kk += 16) {
                wmma::fragment<wmma::matrix_a, 16, 16, 16, __nv_bfloat16, wmma::row_major> a0, a1;
                wmma::load_matrix_sync(a0, sA + (wm * 32) * LDSA + kk, LDSA);
                wmma::load_matrix_sync(a1, sA + (wm * 32 + 16) * LDSA + kk, LDSA);
                if (doRec) {
                    wmma::fragment<wmma::matrix_b, 16, 16, 16, __nv_bfloat16, wmma::row_major> bU;
                    wmma::load_matrix_sync(bU, sUw + kk * LDSU, LDSU);
                    wmma::mma_sync(accR[0], a0, bU, accR[0]);
                    wmma::mma_sync(accR[1], a1, bU, accR[1]);
                }
                if (doZ) {
                    wmma::fragment<wmma::matrix_b, 16, 16, 16, __nv_bfloat16, wmma::row_major> bW;
                    wmma::load_matrix_sync(bW, sWw + kk * LDSU, LDSU);
                    wmma::mma_sync(accZ[0], a0, bW, accZ[0]);
                    wmma::mma_sync(accZ[1], a1, bW, accZ[1]);
                }
            }
        }

        // register epilogue: h_t = tanh(R + Z + b), straight from fragments
        if (doRec) {
            #pragma unroll
            for (int f = 0; f < 2; f++)
                #pragma unroll
                for (int e = 0; e < 4; e++) {
                    size_t addr = base[f * 2 + (e & 1)] + (size_t)it * UNITS + ((e & 2) ? 8 : 0);
                    uint32_t zv = zr[f * 4 + e];
                    __nv_bfloat162 zb = *(__nv_bfloat162*)&zv;
                    float blo = (e & 2) ? bB0 : bA0, bhi = (e & 2) ? bB1 : bA1;
                    __nv_bfloat162 o = __floats2bfloat162_rn(
                        tanhfast(accR[f].x[e * 2]     + __low2float(zb)  + blo),
                        tanhfast(accR[f].x[e * 2 + 1] + __high2float(zb) + bhi));
                    *(__nv_bfloat162*)(g_H + addr) = o;
                }
        }

        const bool needBar = doRec && (hasZ || it < SEQ - 1);
        if (needBar) {
            tgt += 8;
            __syncthreads();              // all h stores issued block-wide
            if (tid == 0) {
                __threadfence();          // release h stores
                atomicAdd(&g_arr[mg], 1u);   // arrive early; Z epilogue fills the gap
            }
        }

        if (doZ) {
            // Z^{l+1}_{it-1} -> g_Z (block-local rows; no cross-block readers yet)
            #pragma unroll
            for (int f = 0; f < 2; f++)
                #pragma unroll
                for (int e = 0; e < 4; e++) {
                    size_t addr = base[f * 2 + (e & 1)] + (size_t)(it - 1) * UNITS + ((e & 2) ? 8 : 0);
                    __nv_bfloat162 o = __floats2bfloat162_rn(accZ[f].x[e * 2], accZ[f].x[e * 2 + 1]);
                    *(__nv_bfloat162*)(g_Z + addr) = o;
                }
        }

        if (needBar) {
            if (tid == 0) {
                volatile unsigned int* p = &g_arr[mg];
                while (*p < tgt) { }
                __threadfence();          // acquire
            }
            __syncthreads();
        } else if (it != itMax) {
            __syncthreads();              // protect A-buffer reuse
        }
    }
}

// ---------------- head ----------------
__global__ void head(const float* __restrict__ Wo, const float* __restrict__ bo,
                     float* __restrict__ out) {
    int gt = blockIdx.x * blockDim.x + threadIdx.x;
    int w = gt >> 5, lane = gt & 31;
    if (w >= BATCH) return;
    const __nv_bfloat16* h = g_H + ((size_t)w * SEQ + (SEQ - 1)) * UNITS;
    float s = 0.f;
    for (int k = lane; k < UNITS; k += 32)
        s += __bfloat162float(h[k]) * Wo[k];
    #pragma unroll
    for (int o = 16; o; o >>= 1) s += __shfl_xor_sync(0xffffffffu, s, o);
    if (lane == 0) out[w] = 1.f / (1.f + expf(-(s + bo[0])));
}

// ---------------- launch ----------------
extern "C" void kernel_launch(void* const* d_in, const int* in_sizes, int n_in,
                              void* d_out, int out_size) {
    const int*   tokens = (const int*)d_in[0];
    const float* emb    = (const float*)d_in[1];
    const float* Wm[4]  = {(const float*)d_in[2],  (const float*)d_in[5],
                           (const float*)d_in[8],  (const float*)d_in[11]};
    const float* Um[4]  = {(const float*)d_in[3],  (const float*)d_in[6],
                           (const float*)d_in[9],  (const float*)d_in[12]};
    const float* bm[4]  = {(const float*)d_in[4],  (const float*)d_in[7],
                           (const float*)d_in[10], (const float*)d_in[13]};
    const float* Wo = (const float*)d_in[14];
    const float* bo = (const float*)d_in[15];
    float* out = (float*)d_out;

    cudaFuncSetAttribute(gemm0,      cudaFuncAttributeMaxDynamicSharedMemorySize, BULK_SMEM);
    cudaFuncSetAttribute(scan_layer, cudaFuncAttributeMaxDynamicSharedMemorySize, SCAN_SMEM);

    void* barAddr = nullptr;
    cudaGetSymbolAddress(&barAddr, g_arr);
    cudaMemsetAsync(barAddr, 0, 16 * sizeof(unsigned int));

    embed_kernel<<<(int)(((size_t)BT * EMBP + 255) / 256), 256>>>(tokens, emb);

    dim3 pg(1024, 8);
    prep_all<<<pg, 256>>>(Wm[0], Wm[1], Wm[2], Wm[3], Um[0], Um[1], Um[2], Um[3]);

    dim3 gin(UNITS / GBN, BT / BM);     // (4, 1280)
    gemm0<<<gin, THREADS, BULK_SMEM>>>();

    for (int l = 0; l < 4; l++) {
        int hasZ = (l < 3) ? 1 : 0;
        scan_layer<<<NBLK, THREADS, SCAN_SMEM>>>(l, bm[l], hasZ, (unsigned)(l * SEQ * 8));
    }
    head<<<(BATCH * 32 + 255) / 256, 256>>>(Wo, bo, out);
}

// round 10
// speedup vs baseline: 1.8859x; 1.5273x over previous
#include <cuda_runtime.h>
#include <cuda_bf16.h>
#include <mma.h>
#include <math.h>
#include <cstdint>

using namespace nvcuda;

#define BATCH 2048
#define SEQ   80
#define UNITS 512
#define EMB   100
#define EMBP  128
#define BT    (BATCH*SEQ)
#define THREADS 512

// ---- scan tiling ----
#define BM 128
#define BN 64
#define NBLK 128                 // 16 m-groups x 8 n-tiles
#define LDSU 72
#define LDSA 72
#define LDSC 68
#define ABUF 18432               // 128*72*2
#define SM_U    0                // 73728
#define SM_W    73728            // 73728
#define SM_A    147456           // 3*18432 = 55296 (sC f32 aliases buf0/1)
#define SM_BIAS 202752
#define SCAN_SMEM 203008

// ---- layer-0 bulk tiling ----
#define GBN 128
#define LDBB 136
#define LDBA 72
#define LDBC 132
#define BULK_ABUF 18432
#define GM_B 0
#define GM_A 139264
#define BULK_SMEM 194560

// ---------------- persistent device scratch (TIME-MAJOR: [t][batch][.]) ----------------
__device__ __nv_bfloat16 g_X[(size_t)BT * EMBP];    // [t*BATCH+b][128]
__device__ __nv_bfloat16 g_Z[(size_t)BT * UNITS];   // [t*BATCH+b][512]
__device__ __nv_bfloat16 g_H[(size_t)BT * UNITS];   // [t*BATCH+b][512]
__device__ __nv_bfloat16 g_W1p[EMBP * UNITS];
__device__ __nv_bfloat16 g_W[3][UNITS * UNITS];     // g_W[l] = Wm[l+1]
__device__ __nv_bfloat16 g_U[4][UNITS * UNITS];
__device__ unsigned int  g_arr[16];

// ---------------- helpers ----------------
__device__ __forceinline__ uint32_t smem_u32(const void* p) {
    uint32_t a;
    asm("{ .reg .u64 t; cvta.to.shared.u64 t, %1; cvt.u32.u64 %0, t; }" : "=r"(a) : "l"(p));
    return a;
}
__device__ __forceinline__ void cp16(uint32_t dst, const void* src) {
    asm volatile("cp.async.cg.shared.global [%0], [%1], 16;" :: "r"(dst), "l"(src));
}
#define CP_COMMIT() asm volatile("cp.async.commit_group;" ::: "memory")
#define CP_WAIT1()  asm volatile("cp.async.wait_group 1;" ::: "memory")
#define CP_WAIT0()  asm volatile("cp.async.wait_group 0;" ::: "memory")

__device__ __forceinline__ void arrive_release(unsigned int* p) {
    asm volatile("red.release.gpu.global.add.u32 [%0], %1;" :: "l"(p), "r"(1u) : "memory");
}
__device__ __forceinline__ unsigned ld_acquire(const unsigned int* p) {
    unsigned v;
    asm volatile("ld.acquire.gpu.global.u32 %0, [%1];" : "=r"(v) : "l"(p) : "memory");
    return v;
}

__device__ __forceinline__ float tanhfast(float x) {
    float y;
    asm("tanh.approx.f32 %0, %1;" : "=f"(y) : "f"(x));
    return y;
}

// ---------------- embed + weight prep ----------------
__global__ void embed_kernel(const int* __restrict__ tokens, const float* __restrict__ emb) {
    size_t idx = (size_t)blockIdx.x * blockDim.x + threadIdx.x;
    if (idx >= (size_t)BT * EMBP) return;
    size_t row = idx >> 7;          // t*BATCH + b
    int col = (int)(idx & 127);
    int t = (int)(row >> 11);       // BATCH = 2048 = 2^11
    int b = (int)(row & 2047);
    int tok = tokens[(size_t)b * SEQ + t];
    float v = (col < EMB) ? emb[(size_t)tok * EMB + col] : 0.f;
    g_X[idx] = __float2bfloat16(v);
}

__global__ void prep_all(const float* __restrict__ W1, const float* __restrict__ W2,
                         const float* __restrict__ W3, const float* __restrict__ W4,
                         const float* __restrict__ U1, const float* __restrict__ U2,
                         const float* __restrict__ U3, const float* __restrict__ U4) {
    int y = blockIdx.y;
    int idx = blockIdx.x * blockDim.x + threadIdx.x;
    if (y == 0) {
        if (idx < EMBP * UNITS) {
            int k = idx >> 9, n = idx & 511;
            g_W1p[idx] = __float2bfloat16(k < EMB ? W1[k * UNITS + n] : 0.f);
        }
    } else if (y <= 3) {
        const float* s = (y == 1) ? W2 : (y == 2) ? W3 : W4;
        if (idx < UNITS * UNITS) g_W[y - 1][idx] = __float2bfloat16(s[idx]);
    } else {
        const float* s = (y == 4) ? U1 : (y == 5) ? U2 : (y == 6) ? U3 : U4;
        if (idx < UNITS * UNITS) g_U[y - 4][idx] = __float2bfloat16(s[idx]);
    }
}

// ---------------- layer-0 bulk GEMM: g_Z = X @ W1p (row index = t*BATCH+b, unchanged math) ----------------
__global__ __launch_bounds__(THREADS, 1) void gemm0() {
    extern __shared__ __align__(16) unsigned char smraw[];
    __nv_bfloat16* sB = (__nv_bfloat16*)(smraw + GM_B);
    float*         sC = (float*)(smraw + GM_B);

    const __nv_bfloat16* Ag = g_X;
    const __nv_bfloat16* Bg = g_W1p;
    const int K = EMBP, aStride = EMBP, KC = 2;

    const int n0 = blockIdx.x * GBN;
    const int m0 = blockIdx.y * BM;
    const int tid = threadIdx.x;
    const int wid = tid >> 5;
    const int wm = wid & 3, wn = wid >> 2;

    const uint32_t sbase = smem_u32(smraw);
    const uint32_t aBase = sbase + GM_A;

    for (int i = tid; i < K * 16; i += THREADS) {
        int r = i >> 4, c = i & 15;
        cp16(sbase + GM_B + r * (LDBB * 2) + c * 16, Bg + (size_t)r * UNITS + n0 + c * 8);
    }
    {
        #pragma unroll
        for (int j = 0; j < 2; j++) {
            int i = tid + j * THREADS;
            int r = i >> 3, c = i & 7;
            cp16(aBase + r * (LDBA * 2) + c * 16, Ag + (size_t)(m0 + r) * aStride + c * 8);
        }
    }
    CP_COMMIT();

    wmma::fragment<wmma::accumulator, 16, 16, 16, float> acc[2][2];
    #pragma unroll
    for (int i = 0; i < 2; i++)
        #pragma unroll
        for (int j = 0; j < 2; j++) wmma::fill_fragment(acc[i][j], 0.f);

    int buf = 0;
    for (int kc = 0; kc < KC; kc++) {
        if (kc + 1 < KC) {
            int nb = buf + 1;
            #pragma unroll
            for (int j = 0; j < 2; j++) {
                int i = tid + j * THREADS;
                int r = i >> 3, c = i & 7;
                cp16(aBase + nb * BULK_ABUF + r * (LDBA * 2) + c * 16,
                     Ag + (size_t)(m0 + r) * aStride + (kc + 1) * 64 + c * 8);
            }
            CP_COMMIT();
            CP_WAIT1();
        } else {
            CP_WAIT0();
        }
        __syncthreads();

        const __nv_bfloat16* sA = (const __nv_bfloat16*)(smraw + GM_A + buf * BULK_ABUF);
        #pragma unroll
        for (int kk = 0; kk < 64; kk += 16) {
            wmma::fragment<wmma::matrix_a, 16, 16, 16, __nv_bfloat16, wmma::row_major> a0, a1;
            wmma::fragment<wmma::matrix_b, 16, 16, 16, __nv_bfloat16, wmma::row_major> b0, b1;
            wmma::load_matrix_sync(a0, sA + (wm * 32) * LDBA + kk, LDBA);
            wmma::load_matrix_sync(a1, sA + (wm * 32 + 16) * LDBA + kk, LDBA);
            wmma::load_matrix_sync(b0, sB + (kc * 64 + kk) * LDBB + wn * 32, LDBB);
            wmma::load_matrix_sync(b1, sB + (kc * 64 + kk) * LDBB + wn * 32 + 16, LDBB);
            wmma::mma_sync(acc[0][0], a0, b0, acc[0][0]);
            wmma::mma_sync(acc[0][1], a0, b1, acc[0][1]);
            wmma::mma_sync(acc[1][0], a1, b0, acc[1][0]);
            wmma::mma_sync(acc[1][1], a1, b1, acc[1][1]);
        }
        buf++;
    }
    __syncthreads();

    #pragma unroll
    for (int i = 0; i < 2; i++)
        #pragma unroll
        for (int j = 0; j < 2; j++)
            wmma::store_matrix_sync(&sC[(wm * 32 + i * 16) * LDBC + wn * 32 + j * 16],
                                    acc[i][j], LDBC, wmma::mem_row_major);
    __syncthreads();

    {
        const int erow = tid >> 2;
        const int ecb  = (tid & 3) * 32;
        const float* s = &sC[erow * LDBC + ecb];
        __nv_bfloat162 p[16];
        #pragma unroll
        for (int q = 0; q < 16; q++) p[q] = __floats2bfloat162_rn(s[2*q], s[2*q+1]);
        __nv_bfloat16* dst = g_Z + (size_t)(m0 + erow) * UNITS + n0 + ecb;
        #pragma unroll
        for (int q = 0; q < 4; q++)
            *(uint4*)(dst + q * 8) = *(uint4*)&p[q * 4];
    }
}

// ---------------- fused persistent scan (R7 structure, time-major, rel/acq barrier) ----------------
__global__ __launch_bounds__(THREADS, 1)
void scan_layer(int layer, const float* __restrict__ bias, int hasZ, unsigned barBase) {
    extern __shared__ __align__(16) unsigned char smraw[];
    __nv_bfloat16* sU = (__nv_bfloat16*)(smraw + SM_U);
    __nv_bfloat16* sW = (__nv_bfloat16*)(smraw + SM_W);
    float*         sC = (float*)(smraw + SM_A);
    float*         sBias = (float*)(smraw + SM_BIAS);
    const uint32_t aBase = smem_u32(smraw) + SM_A;

    const int tid = threadIdx.x;
    const int wid = tid >> 5;
    const int bid = blockIdx.x;
    const int n0 = (bid & 7) * BN;
    const int mg = bid >> 3;
    const int m0 = mg * BM;
    const int wm = wid & 3, wn = wid >> 2;

    // stage U and (if hasZ) Wnext
    {
        const __nv_bfloat16* U = g_U[layer];
        #pragma unroll
        for (int j = 0; j < 8; j++) {
            int i = tid + j * THREADS;
            int r = i >> 3, c = i & 7;
            *(uint4*)&sU[r * LDSU + c * 8] = *(const uint4*)(U + (size_t)r * UNITS + n0 + c * 8);
        }
        if (hasZ) {
            const __nv_bfloat16* W = g_W[layer];
            #pragma unroll
            for (int j = 0; j < 8; j++) {
                int i = tid + j * THREADS;
                int r = i >> 3, c = i & 7;
                *(uint4*)&sW[r * LDSU + c * 8] = *(const uint4*)(W + (size_t)r * UNITS + n0 + c * 8);
            }
        }
        if (tid < BN) sBias[tid] = bias[n0 + tid];
    }
    __syncthreads();

    const int erow = (wid & 3) * 32 + (tid & 31);
    const int ecb  = (wid >> 2) * 16;
    const int bRow = m0 + erow;                 // this thread's batch row
    const int itMax = hasZ ? SEQ : (SEQ - 1);
    unsigned tgt = barBase;

    for (int it = 0; it <= itMax; it++) {
        const bool doRec = (it < SEQ);
        const bool doZ   = (hasZ && it >= 1);

        if (it == 0) {
            // h_0 = tanh(Z_0 + b)   (slab 0)
            size_t eidx = (size_t)bRow * UNITS + n0 + ecb;
            uint4 z0 = *(const uint4*)(g_Z + eidx);
            uint4 z1 = *(const uint4*)(g_Z + eidx + 8);
            __nv_bfloat162 zb[8];
            *(uint4*)&zb[0] = z0; *(uint4*)&zb[4] = z1;
            __nv_bfloat162 o[8];
            #pragma unroll
            for (int c = 0; c < 8; c++)
                o[c] = __floats2bfloat162_rn(tanhfast(__low2float(zb[c])  + sBias[ecb + 2*c]),
                                             tanhfast(__high2float(zb[c]) + sBias[ecb + 2*c + 1]));
            __nv_bfloat16* dst = g_H + eidx;
            *(uint4*)dst       = *(uint4*)&o[0];
            *(uint4*)(dst + 8) = *(uint4*)&o[4];

            tgt += 8;
            __syncthreads();
            if (tid == 0) {
                arrive_release(&g_arr[mg]);
                while (ld_acquire(&g_arr[mg]) < tgt) { }
            }
            __syncthreads();
            continue;
        }

        // A = h_{it-1} slab (contiguous 2 MB; block reads 128KB contiguous)
        const __nv_bfloat16* A = g_H + (size_t)(it - 1) * BATCH * UNITS + (size_t)m0 * UNITS;

        // prologue: A chunks 0,1
        #pragma unroll
        for (int cidx = 0; cidx < 2; cidx++) {
            #pragma unroll
            for (int j = 0; j < 2; j++) {
                int i = tid + j * THREADS;
                int r = i >> 3, c = i & 7;
                cp16(aBase + cidx * ABUF + r * (LDSA * 2) + c * 16,
                     A + (size_t)r * UNITS + cidx * 64 + c * 8);
            }
            CP_COMMIT();
        }

        // own-Z prefetch
        uint4 zr0, zr1;
        if (doRec) {
            const uint4* zp = (const uint4*)(g_Z + ((size_t)it * BATCH + bRow) * UNITS + n0 + ecb);
            zr0 = zp[0]; zr1 = zp[1];
        }

        wmma::fragment<wmma::accumulator, 16, 16, 16, float> accR[2], accZ[2];
        if (doRec) { wmma::fill_fragment(accR[0], 0.f); wmma::fill_fragment(accR[1], 0.f); }
        if (doZ)   { wmma::fill_fragment(accZ[0], 0.f); wmma::fill_fragment(accZ[1], 0.f); }

        for (int kc = 0; kc < 8; kc++) {
            if (kc < 7) CP_WAIT1(); else CP_WAIT0();
            __syncthreads();
            if (kc + 2 < 8) {
                int nb = (kc + 2) % 3;
                #pragma unroll
                for (int j = 0; j < 2; j++) {
                    int i = tid + j * THREADS;
                    int r = i >> 3, c = i & 7;
                    cp16(aBase + nb * ABUF + r * (LDSA * 2) + c * 16,
                         A + (size_t)r * UNITS + (kc + 2) * 64 + c * 8);
                }
                CP_COMMIT();
            }
            const __nv_bfloat16* sA  = (const __nv_bfloat16*)(smraw + SM_A + (kc % 3) * ABUF);
            const __nv_bfloat16* sUw = sU + (kc * 64) * LDSU + wn * 16;
            const __nv_bfloat16* sWw = sW + (kc * 64) * LDSU + wn * 16;
            #pragma unroll
            for (int kk = 0; kk < 64; kk += 16) {
                wmma::fragment<wmma::matrix_a, 16, 16, 16, __nv_bfloat16, wmma::row_major> a0, a1;
                wmma::load_matrix_sync(a0, sA + (wm * 32) * LDSA + kk, LDSA);
                wmma::load_matrix_sync(a1, sA + (wm * 32 + 16) * LDSA + kk, LDSA);
                if (doRec) {
                    wmma::fragment<wmma::matrix_b, 16, 16, 16, __nv_bfloat16, wmma::row_major> bU;
                    wmma::load_matrix_sync(bU, sUw + kk * LDSU, LDSU);
                    wmma::mma_sync(accR[0], a0, bU, accR[0]);
                    wmma::mma_sync(accR[1], a1, bU, accR[1]);
                }
                if (doZ) {
                    wmma::fragment<wmma::matrix_b, 16, 16, 16, __nv_bfloat16, wmma::row_major> bW;
                    wmma::load_matrix_sync(bW, sWw + kk * LDSU, LDSU);
                    wmma::mma_sync(accZ[0], a0, bW, accZ[0]);
                    wmma::mma_sync(accZ[1], a1, bW, accZ[1]);
                }
            }
        }
        __syncthreads();   // MMA done; A buffers (sC alias) free

        if (doRec) {
            // h_t = tanh(R + Z + b) via coalescing smem stage
            wmma::store_matrix_sync(&sC[(wm * 32) * LDSC + wn * 16],      accR[0], LDSC, wmma::mem_row_major);
            wmma::store_matrix_sync(&sC[(wm * 32 + 16) * LDSC + wn * 16], accR[1], LDSC, wmma::mem_row_major);
            __syncthreads();
            const float* s = &sC[erow * LDSC + ecb];
            __nv_bfloat162 zb[8];
            *(uint4*)&zb[0] = zr0; *(uint4*)&zb[4] = zr1;
            __nv_bfloat162 o[8];
            size_t eidx = ((size_t)it * BATCH + bRow) * UNITS + n0 + ecb;
            #pragma unroll
            for (int c = 0; c < 8; c++)
                o[c] = __floats2bfloat162_rn(
                    tanhfast(s[2*c]     + __low2float(zb[c])  + sBias[ecb + 2*c]),
                    tanhfast(s[2*c + 1] + __high2float(zb[c]) + sBias[ecb + 2*c + 1]));
            __nv_bfloat16* dst = g_H + eidx;
            *(uint4*)dst       = *(uint4*)&o[0];
            *(uint4*)(dst + 8) = *(uint4*)&o[4];
        }

        const bool needBar = doRec && (hasZ || it < SEQ - 1);
        if (needBar) {
            tgt += 8;
            __syncthreads();              // h stores issued + sC reads done
            if (tid == 0) arrive_release(&g_arr[mg]);   // early arrive; Z fills the gap
        }

        if (doZ) {
            // Z^{l+1}_{it-1} -> g_Z (block-local rows)
            wmma::store_matrix_sync(&sC[(wm * 32) * LDSC + wn * 16],      accZ[0], LDSC, wmma::mem_row_major);
            wmma::store_matrix_sync(&sC[(wm * 32 + 16) * LDSC + wn * 16], accZ[1], LDSC, wmma::mem_row_major);
            __syncthreads();
            const float* s = &sC[erow * LDSC + ecb];
            __nv_bfloat162 o[8];
            #pragma unroll
            for (int c = 0; c < 8; c++)
                o[c] = __floats2bfloat162_rn(s[2*c], s[2*c + 1]);
            __nv_bfloat16* dst = g_Z + ((size_t)(it - 1) * BATCH + bRow) * UNITS + n0 + ecb;
            *(uint4*)dst       = *(uint4*)&o[0];
            *(uint4*)(dst + 8) = *(uint4*)&o[4];
        }

        if (needBar) {
            if (tid == 0) {
                while (ld_acquire(&g_arr[mg]) < tgt) { }
            }
            __syncthreads();
        } else if (it != itMax) {
            __syncthreads();
        }
    }
}

// ---------------- head ----------------
__global__ void head(const float* __restrict__ Wo, const float* __restrict__ bo,
                     float* __restrict__ out) {
    int gt = blockIdx.x * blockDim.x + threadIdx.x;
    int w = gt >> 5, lane = gt & 31;
    if (w >= BATCH) return;
    const __nv_bfloat16* h = g_H + ((size_t)(SEQ - 1) * BATCH + w) * UNITS;
    float s = 0.f;
    for (int k = lane; k < UNITS; k += 32)
        s += __bfloat162float(h[k]) * Wo[k];
    #pragma unroll
    for (int o = 16; o; o >>= 1) s += __shfl_xor_sync(0xffffffffu, s, o);
    if (lane == 0) out[w] = 1.f / (1.f + expf(-(s + bo[0])));
}

// ---------------- launch ----------------
extern "C" void kernel_launch(void* const* d_in, const int* in_sizes, int n_in,
                              void* d_out, int out_size) {
    const int*   tokens = (const int*)d_in[0];
    const float* emb    = (const float*)d_in[1];
    const float* Wm[4]  = {(const float*)d_in[2],  (const float*)d_in[5],
                           (const float*)d_in[8],  (const float*)d_in[11]};
    const float* Um[4]  = {(const float*)d_in[3],  (const float*)d_in[6],
                           (const float*)d_in[9],  (const float*)d_in[12]};
    const float* bm[4]  = {(const float*)d_in[4],  (const float*)d_in[7],
                           (const float*)d_in[10], (const float*)d_in[13]};
    const float* Wo = (const float*)d_in[14];
    const float* bo = (const float*)d_in[15];
    float* out = (float*)d_out;

    cudaFuncSetAttribute(gemm0,      cudaFuncAttributeMaxDynamicSharedMemorySize, BULK_SMEM);
    cudaFuncSetAttribute(scan_layer, cudaFuncAttributeMaxDynamicSharedMemorySize, SCAN_SMEM);

    void* barAddr = nullptr;
    cudaGetSymbolAddress(&barAddr, g_arr);
    cudaMemsetAsync(barAddr, 0, 16 * sizeof(unsigned int));

    embed_kernel<<<(int)(((size_t)BT * EMBP + 255) / 256), 256>>>(tokens, emb);

    dim3 pg(1024, 8);
    prep_all<<<pg, 256>>>(Wm[0], Wm[1], Wm[2], Wm[3], Um[0], Um[1], Um[2], Um[3]);

    dim3 gin(UNITS / GBN, BT / BM);     // (4, 1280)
    gemm0<<<gin, THREADS, BULK_SMEM>>>();

    for (int l = 0; l < 4; l++) {
        int hasZ = (l < 3) ? 1 : 0;
        scan_layer<<<NBLK, THREADS, SCAN_SMEM>>>(l, bm[l], hasZ, (unsigned)(l * SEQ * 8));
    }
    head<<<(BATCH * 32 + 255) / 256, 256>>>(Wo, bo, out);
}